// round 9
// baseline (speedup 1.0000x reference)
#include <cuda_runtime.h>
#include <math.h>

// ============================================================================
// PhasorTransformer, linear-algebra collapsed form.
//
// zf[0] = e^{i w31[0]} * sum_t e^{i w00[t]} * r[t] * e^{i x[t]},
//   r = F(m1 .* F(m2 .* F(m3)))  (F = unnormalized DFT, F^T = F; ortho
//   scalings drop out of angle; asin(sin(.)) = exact triangular wrap).
//
// Kernel 1 (1 block x 128 thr): r'' via radix-16*16*8 FFTs (9 barriers).
// Kernel 2: complex dot, 2 rows/warp (shared table reads, doubled independent
//   FMA/MUFU streams), r'' in smem, float4 streaming loads.
// ============================================================================

#define NFFT 2048
#define PTPB 128
#define PADI(i) ((i) + ((i) >> 5))

__device__ float g_rre[NFFT];
__device__ float g_rim[NFFT];

// ---------------------------------------------------------------- complex ops
__device__ __forceinline__ float2 cmul(float2 a, float2 b) {
    return make_float2(fmaf(a.x, b.x, -a.y * b.y), fmaf(a.x, b.y, a.y * b.x));
}
__device__ __forceinline__ float2 cadd(float2 a, float2 b) { return make_float2(a.x + b.x, a.y + b.y); }
__device__ __forceinline__ float2 csub(float2 a, float2 b) { return make_float2(a.x - b.x, a.y - b.y); }
__device__ __forceinline__ float2 mulnegi(float2 a) { return make_float2(a.y, -a.x); }

__device__ __forceinline__ void dft4(float2& a0, float2& a1, float2& a2, float2& a3) {
    float2 t0 = cadd(a0, a2), t1 = csub(a0, a2);
    float2 t2 = cadd(a1, a3), t3 = csub(a1, a3);
    a0 = cadd(t0, t2);
    a2 = csub(t0, t2);
    float2 it3 = mulnegi(t3);
    a1 = cadd(t1, it3);
    a3 = csub(t1, it3);
}

// forward DFT16 (DIF 4x4). Output X[k1+4*k2] at v[4*k1+k2].
__device__ __forceinline__ void dft16(float2 v[16]) {
    const float C1 = 0.92387953251128675f;
    const float S1 = 0.38268343236508977f;
    const float R2 = 0.70710678118654752f;
#pragma unroll
    for (int j2 = 0; j2 < 4; j2++)
        dft4(v[j2], v[j2 + 4], v[j2 + 8], v[j2 + 12]);
    v[5]  = cmul(v[5],  make_float2( C1, -S1));
    v[9]  = cmul(v[9],  make_float2( R2, -R2));
    v[13] = cmul(v[13], make_float2( S1, -C1));
    v[6]  = cmul(v[6],  make_float2( R2, -R2));
    v[10] = mulnegi(v[10]);
    v[14] = cmul(v[14], make_float2(-R2, -R2));
    v[7]  = cmul(v[7],  make_float2( S1, -C1));
    v[11] = cmul(v[11], make_float2(-R2, -R2));
    v[15] = cmul(v[15], make_float2(-C1,  S1));
#pragma unroll
    for (int k1 = 0; k1 < 4; k1++)
        dft4(v[4 * k1], v[4 * k1 + 1], v[4 * k1 + 2], v[4 * k1 + 3]);
}

__device__ __forceinline__ void dft8(float2* a, float2* o) {
    const float R2 = 0.70710678118654752f;
    dft4(a[0], a[2], a[4], a[6]);
    dft4(a[1], a[3], a[5], a[7]);
    a[3] = cmul(a[3], make_float2(R2, -R2));
    a[5] = mulnegi(a[5]);
    a[7] = cmul(a[7], make_float2(-R2, -R2));
#pragma unroll
    for (int k1 = 0; k1 < 4; k1++) {
        o[k1]     = cadd(a[2 * k1], a[2 * k1 + 1]);
        o[k1 + 4] = csub(a[2 * k1], a[2 * k1 + 1]);
    }
}

// dft16 + outer twiddle w1^f (depth-4 power tree) + store at dst[f*128+t].
__device__ __forceinline__ void pass_store(float2 v[16], int t, float2 w1,
                                           float* dre, float* dim) {
    dft16(v);
    float2 tw[16];
    tw[1] = w1;
    tw[2] = cmul(tw[1], tw[1]);
    tw[3] = cmul(tw[2], tw[1]);
    tw[4] = cmul(tw[2], tw[2]);
    tw[5] = cmul(tw[4], tw[1]);
    tw[6] = cmul(tw[4], tw[2]);
    tw[7] = cmul(tw[4], tw[3]);
    tw[8] = cmul(tw[4], tw[4]);
#pragma unroll
    for (int f = 9; f < 16; f++) tw[f] = cmul(tw[8], tw[f - 8]);

    constexpr int idx16[16] = {0, 4, 8, 12, 1, 5, 9, 13, 2, 6, 10, 14, 3, 7, 11, 15};
    {
        int a = PADI(t);
        dre[a] = v[0].x; dim[a] = v[0].y;
    }
#pragma unroll
    for (int f = 1; f < 16; f++) {
        float2 val = cmul(v[idx16[f]], tw[f]);
        int a = PADI(f * PTPB + t);
        dre[a] = val.x; dim[a] = val.y;
    }
}

__device__ __forceinline__ void load_p1(float2 v[16], int t,
                                        const float* sre, const float* sim) {
#pragma unroll
    for (int j = 0; j < 16; j++) {
        int a = PADI(t + PTPB * j);
        v[j] = make_float2(sre[a], sim[a]);
    }
}

__device__ __forceinline__ void load_p2(float2 v[16], int t,
                                        const float* sre, const float* sim) {
    int base = (t >> 3) * PTPB + (t & 7);
#pragma unroll
    for (int j = 0; j < 16; j++) {
        int a = PADI(base + 8 * j);
        v[j] = make_float2(sre[a], sim[a]);
    }
}

__device__ __forceinline__ void load_p3(float2 v[16], int t,
                                        const float* sre, const float* sim) {
#pragma unroll
    for (int i = 0; i < 2; i++) {
        int q = t + PTPB * i;
#pragma unroll
        for (int j = 0; j < 8; j++) {
            int a = PADI(q * 8 + j);
            v[8 * i + j] = make_float2(sre[a], sim[a]);
        }
    }
}

// final radix-8 + multiply exp(i(w[o1+g]+w[o2+g])) + natural-order scatter
__device__ __forceinline__ void p3_store_mul(float2 v[16], int t,
                                             const float* __restrict__ w,
                                             int o1, int o2,
                                             float* dre, float* dim) {
#pragma unroll
    for (int i = 0; i < 2; i++) {
        int q = t + PTPB * i;
        float2 o[8];
        dft8(v + 8 * i, o);
#pragma unroll
        for (int d = 0; d < 8; d++) {
            int g = q + 256 * d;
            float s, c;
            sincosf(w[o1 + g] + w[o2 + g], &s, &c);
            float2 val = cmul(o[d], make_float2(c, s));
            int a = PADI(g);
            dre[a] = val.x; dim[a] = val.y;
        }
    }
}

// ---------------------------------------------------------------- precompute
__global__ void __launch_bounds__(PTPB)
precompute_kernel(const float* __restrict__ w) {
    __shared__ float Are[2112], Aim[2112];
    __shared__ float Bre[2112], Bim[2112];
    const int t = threadIdx.x;
    float2 v[16];

    // v = m3 = exp(i(w21 + w30))
#pragma unroll
    for (int j = 0; j < 16; j++) {
        int e = t + PTPB * j;
        float s, c;
        sincosf(w[10240 + e] + w[12288 + e], &s, &c);
        v[j] = make_float2(c, s);
    }
    float s1, c1, s2, c2;
    sincosf(-6.2831853071795864769f * (float)t / 2048.0f, &s1, &c1);
    sincosf(-6.2831853071795864769f * (float)(t & 7) / 128.0f, &s2, &c2);
    const float2 tw_p1 = make_float2(c1, s1);
    const float2 tw_p2 = make_float2(c2, s2);

    // FFT #1 (of m3), then .* m2
    pass_store(v, t, tw_p1, Are, Aim);                          __syncthreads();
    load_p2(v, t, Are, Aim); pass_store(v, t, tw_p2, Bre, Bim); __syncthreads();
    load_p3(v, t, Bre, Bim); p3_store_mul(v, t, w, 6144, 8192, Are, Aim); __syncthreads();

    // FFT #2, then .* m1
    load_p1(v, t, Are, Aim); pass_store(v, t, tw_p1, Bre, Bim); __syncthreads();
    load_p2(v, t, Bre, Bim); pass_store(v, t, tw_p2, Are, Aim); __syncthreads();
    load_p3(v, t, Are, Aim); p3_store_mul(v, t, w, 2048, 4096, Bre, Bim); __syncthreads();

    // FFT #3, then fold exp(i(w00[g] + w31[0])) and publish
    load_p1(v, t, Bre, Bim); pass_store(v, t, tw_p1, Are, Aim); __syncthreads();
    load_p2(v, t, Are, Aim); pass_store(v, t, tw_p2, Bre, Bim); __syncthreads();
    load_p3(v, t, Bre, Bim);

    const float w310 = w[14336];
#pragma unroll
    for (int i = 0; i < 2; i++) {
        int q = t + PTPB * i;
        float2 o[8];
        dft8(v + 8 * i, o);
#pragma unroll
        for (int d = 0; d < 8; d++) {
            int g = q + 256 * d;
            float s, c;
            sincosf(w[g] + w310, &s, &c);
            float2 val = cmul(o[d], make_float2(c, s));
            g_rre[g] = val.x;
            g_rim[g] = val.y;
        }
    }
}

// ---------------------------------------------------------------- main kernel
#define TPB 256
#define WPB (TPB / 32)
#define RPB (2 * WPB)

__global__ void __launch_bounds__(TPB)
dot_kernel(const float* __restrict__ x, float* __restrict__ out, int rows) {
    __shared__ float sR[NFFT], sI[NFFT];
    const int tid = threadIdx.x;
    for (int i = tid; i < NFFT; i += TPB) {
        sR[i] = g_rre[i];
        sI[i] = g_rim[i];
    }
    __syncthreads();

    const int warp = tid >> 5;
    const int lane = tid & 31;
    const float4* sR4 = (const float4*)sR;
    const float4* sI4 = (const float4*)sI;

    for (int base = blockIdx.x * RPB + warp * 2; base < rows; base += gridDim.x * RPB) {
        const int row1 = (base + 1 < rows) ? (base + 1) : base;   // clamp: in-bounds
        const float4* xr0 = (const float4*)(x + (size_t)base * NFFT);
        const float4* xr1 = (const float4*)(x + (size_t)row1 * NFFT);
        float ax0 = 0.f, ay0 = 0.f, ax1 = 0.f, ay1 = 0.f;
#pragma unroll
        for (int j = 0; j < 16; j++) {
            int e4 = lane + 32 * j;
            float4 xv0 = __ldcs(&xr0[e4]);
            float4 xv1 = __ldcs(&xr1[e4]);
            float4 rr = sR4[e4];
            float4 ri = sI4[e4];
            float s, c;
            __sincosf(xv0.x, &s, &c);
            ax0 = fmaf(rr.x, c, ax0); ax0 = fmaf(-ri.x, s, ax0);
            ay0 = fmaf(rr.x, s, ay0); ay0 = fmaf( ri.x, c, ay0);
            __sincosf(xv1.x, &s, &c);
            ax1 = fmaf(rr.x, c, ax1); ax1 = fmaf(-ri.x, s, ax1);
            ay1 = fmaf(rr.x, s, ay1); ay1 = fmaf( ri.x, c, ay1);
            __sincosf(xv0.y, &s, &c);
            ax0 = fmaf(rr.y, c, ax0); ax0 = fmaf(-ri.y, s, ax0);
            ay0 = fmaf(rr.y, s, ay0); ay0 = fmaf( ri.y, c, ay0);
            __sincosf(xv1.y, &s, &c);
            ax1 = fmaf(rr.y, c, ax1); ax1 = fmaf(-ri.y, s, ax1);
            ay1 = fmaf(rr.y, s, ay1); ay1 = fmaf( ri.y, c, ay1);
            __sincosf(xv0.z, &s, &c);
            ax0 = fmaf(rr.z, c, ax0); ax0 = fmaf(-ri.z, s, ax0);
            ay0 = fmaf(rr.z, s, ay0); ay0 = fmaf( ri.z, c, ay0);
            __sincosf(xv1.z, &s, &c);
            ax1 = fmaf(rr.z, c, ax1); ax1 = fmaf(-ri.z, s, ax1);
            ay1 = fmaf(rr.z, s, ay1); ay1 = fmaf( ri.z, c, ay1);
            __sincosf(xv0.w, &s, &c);
            ax0 = fmaf(rr.w, c, ax0); ax0 = fmaf(-ri.w, s, ax0);
            ay0 = fmaf(rr.w, s, ay0); ay0 = fmaf( ri.w, c, ay0);
            __sincosf(xv1.w, &s, &c);
            ax1 = fmaf(rr.w, c, ax1); ax1 = fmaf(-ri.w, s, ax1);
            ay1 = fmaf(rr.w, s, ay1); ay1 = fmaf( ri.w, c, ay1);
        }
#pragma unroll
        for (int off = 16; off > 0; off >>= 1) {
            ax0 += __shfl_xor_sync(0xffffffffu, ax0, off);
            ay0 += __shfl_xor_sync(0xffffffffu, ay0, off);
            ax1 += __shfl_xor_sync(0xffffffffu, ax1, off);
            ay1 += __shfl_xor_sync(0xffffffffu, ay1, off);
        }
        if (lane == 0) {
            const float PI_F = 3.14159265358979323846f;
            const float HPI  = 1.57079632679489661923f;
            float th0 = atan2f(ay0, ax0);
            if (th0 >  HPI)      th0 =  PI_F - th0;
            else if (th0 < -HPI) th0 = -PI_F - th0;
            out[base] = th0;
            if (row1 != base) {
                float th1 = atan2f(ay1, ax1);
                if (th1 >  HPI)      th1 =  PI_F - th1;
                else if (th1 < -HPI) th1 = -PI_F - th1;
                out[row1] = th1;
            }
        }
    }
}

// ---------------------------------------------------------------- launch
extern "C" void kernel_launch(void* const* d_in, const int* in_sizes, int n_in,
                              void* d_out, int out_size) {
    const float* x = (const float*)d_in[0];
    const float* w = (const float*)d_in[1];
    float* out = (float*)d_out;
    const int rows = in_sizes[0] / NFFT;
    if (rows <= 0) return;

    precompute_kernel<<<1, PTPB>>>(w);

    int grid = (rows + RPB - 1) / RPB;
    dot_kernel<<<grid, TPB>>>(x, out, rows);
}

// round 11
// speedup vs baseline: 1.2832x; 1.2832x over previous
#include <cuda_runtime.h>
#include <math.h>

// ============================================================================
// PhasorTransformer, linear-algebra collapsed form.
//
// zf[0] = e^{i w31[0]} * sum_t e^{i w00[t]} * r[t] * e^{i x[t]},
//   r = F(m1 .* F(m2 .* F(m3)))  (F = unnormalized DFT, F^T = F; ortho
//   scalings drop out of angle; asin(sin(.)) = exact triangular wrap).
//
// Precompute = 1024-thread Stockham with RADIX-4 fused stages (verified by
// symbolic composition of two radix-2 stages): 6 barriers/FFT, 20 total.
// Dot kernel = byte-for-byte the fastest measured variant (R5: TPB 512, __ldg).
// ============================================================================

#define NFFT 2048

__device__ float g_rre[NFFT];
__device__ float g_rim[NFFT];

// ---------------------------------------------------------------- precompute
#define PRE_T 1024

__global__ void __launch_bounds__(PRE_T)
precompute_kernel(const float* __restrict__ w) {
    __shared__ float br[2][NFFT];
    __shared__ float bi[2][NFFT];
    __shared__ float twr[NFFT / 2];
    __shared__ float twi[NFFT / 2];
    const int tid = threadIdx.x;

    {   // twiddles exp(-2*pi*i*k/2048), k < 1024
        float a = -6.2831853071795864769f * (float)tid / (float)NFFT;
        float s, c;
        sincosf(a, &s, &c);
        twr[tid] = c;
        twi[tid] = s;
    }
    // buffer 0 = m3 = exp(i(w21 + w30))
#pragma unroll
    for (int k = 0; k < 2; k++) {
        int e = tid + PRE_T * k;
        float a = w[10240 + e] + w[12288 + e];
        float s, c;
        sincosf(a, &s, &c);
        br[0][e] = c;
        bi[0][e] = s;
    }
    __syncthreads();

    int cur = 0;
    for (int f = 0; f < 3; f++) {
        // 5 radix-4 stages: s = 1, 4, 16, 64, 256
        for (int st = 0; st < 5; st++) {
            const int sh = 2 * st;
            const int s = 1 << sh;
            const int nxt = cur ^ 1;
            if (tid < 512) {
                const int p = tid >> sh;
                const int q = tid & (s - 1);
                float ar = br[cur][tid],         ai = bi[cur][tid];
                float cr = br[cur][tid + 512],   ci = bi[cur][tid + 512];
                float brr = br[cur][tid + 1024], bii = bi[cur][tid + 1024];
                float dr = br[cur][tid + 1536],  di = bi[cur][tid + 1536];
                const int i1 = p << sh;        // p*s
                const int i2 = i1 << 1;        // 2*p*s (< 1024)
                float w1r = twr[i1], w1i = twi[i1];
                float w2r = twr[i2], w2i = twi[i2];

                // u0=a+b; u1=(a-b)w1; u2=c+d; u3=-i(c-d)w1
                float u0r = ar + brr, u0i = ai + bii;
                float t1r = ar - brr, t1i = ai - bii;
                float u1r = fmaf(t1r, w1r, -t1i * w1i);
                float u1i = fmaf(t1r, w1i,  t1i * w1r);
                float u2r = cr + dr,  u2i = ci + di;
                float t3r = cr - dr,  t3i = ci - di;
                float v3r = fmaf(t3r, w1r, -t3i * w1i);
                float v3i = fmaf(t3r, w1i,  t3i * w1r);
                float u3r =  v3i;
                float u3i = -v3r;

                const int o = q + (p << (sh + 2));   // q + 4*p*s
                br[nxt][o]         = u0r + u2r;
                bi[nxt][o]         = u0i + u2i;
                br[nxt][o + s]     = u1r + u3r;
                bi[nxt][o + s]     = u1i + u3i;
                float e0r = u0r - u2r, e0i = u0i - u2i;
                br[nxt][o + 2 * s] = fmaf(e0r, w2r, -e0i * w2i);
                bi[nxt][o + 2 * s] = fmaf(e0r, w2i,  e0i * w2r);
                float e1r = u1r - u3r, e1i = u1i - u3i;
                br[nxt][o + 3 * s] = fmaf(e1r, w2r, -e1i * w2i);
                bi[nxt][o + 3 * s] = fmaf(e1r, w2i,  e1i * w2r);
            }
            cur = nxt;
            __syncthreads();
        }
        // final radix-2 stage, s = 1024 (twiddle = 1)
        {
            const int nxt = cur ^ 1;
            float ar = br[cur][tid],         ai = bi[cur][tid];
            float brr = br[cur][tid + 1024], bii = bi[cur][tid + 1024];
            br[nxt][tid]        = ar + brr;
            bi[nxt][tid]        = ai + bii;
            br[nxt][tid + 1024] = ar - brr;
            bi[nxt][tid + 1024] = ai - bii;
            cur = nxt;
            __syncthreads();
        }
        // inter-FFT phase multiply (f=0: m2, f=1: m1)
        if (f < 2) {
            const int o1 = (f == 0) ? 6144 : 2048;
            const int o2 = (f == 0) ? 8192 : 4096;
#pragma unroll
            for (int k = 0; k < 2; k++) {
                int e = tid + PRE_T * k;
                float a = w[o1 + e] + w[o2 + e];
                float s, c;
                sincosf(a, &s, &c);
                float vr = br[cur][e], vi = bi[cur][e];
                br[cur][e] = fmaf(vr, c, -vi * s);
                bi[cur][e] = fmaf(vr, s,  vi * c);
            }
            __syncthreads();
        }
    }

    // fold exp(i*(w00[e] + w31[0])), publish r''
    const float w310 = w[14336];
#pragma unroll
    for (int k = 0; k < 2; k++) {
        int e = tid + PRE_T * k;
        float a = w[e] + w310;
        float s, c;
        sincosf(a, &s, &c);
        float vr = br[cur][e], vi = bi[cur][e];
        g_rre[e] = fmaf(vr, c, -vi * s);
        g_rim[e] = fmaf(vr, s,  vi * c);
    }
}

// ---------------------------------------------------------------- main kernel
// warp-per-row complex dot product: S = sum_t r''[t] e^{i x[t]}   (R5 exact)
#define TPB 512
#define WPB (TPB / 32)

__global__ void __launch_bounds__(TPB)
dot_kernel(const float* __restrict__ x, float* __restrict__ out, int rows) {
    __shared__ float sR[NFFT], sI[NFFT];
    const int tid = threadIdx.x;
    for (int i = tid; i < NFFT; i += TPB) {
        sR[i] = g_rre[i];
        sI[i] = g_rim[i];
    }
    __syncthreads();

    const int warp = tid >> 5;
    const int lane = tid & 31;
    const float4* sR4 = (const float4*)sR;
    const float4* sI4 = (const float4*)sI;

    for (int row = blockIdx.x * WPB + warp; row < rows; row += gridDim.x * WPB) {
        const float4* xr = (const float4*)(x + (size_t)row * NFFT);
        float ax = 0.f, ay = 0.f;
#pragma unroll
        for (int j = 0; j < 16; j++) {
            int e4 = lane + 32 * j;            // float4 index (512 per row)
            float4 xv = __ldg(&xr[e4]);
            float4 rr = sR4[e4];
            float4 ri = sI4[e4];
            float s, c;
            __sincosf(xv.x, &s, &c);
            ax = fmaf(rr.x, c, ax); ax = fmaf(-ri.x, s, ax);
            ay = fmaf(rr.x, s, ay); ay = fmaf( ri.x, c, ay);
            __sincosf(xv.y, &s, &c);
            ax = fmaf(rr.y, c, ax); ax = fmaf(-ri.y, s, ax);
            ay = fmaf(rr.y, s, ay); ay = fmaf( ri.y, c, ay);
            __sincosf(xv.z, &s, &c);
            ax = fmaf(rr.z, c, ax); ax = fmaf(-ri.z, s, ax);
            ay = fmaf(rr.z, s, ay); ay = fmaf( ri.z, c, ay);
            __sincosf(xv.w, &s, &c);
            ax = fmaf(rr.w, c, ax); ax = fmaf(-ri.w, s, ax);
            ay = fmaf(rr.w, s, ay); ay = fmaf( ri.w, c, ay);
        }
#pragma unroll
        for (int off = 16; off > 0; off >>= 1) {
            ax += __shfl_xor_sync(0xffffffffu, ax, off);
            ay += __shfl_xor_sync(0xffffffffu, ay, off);
        }
        if (lane == 0) {
            float th = atan2f(ay, ax);
            const float PI_F = 3.14159265358979323846f;
            const float HPI  = 1.57079632679489661923f;
            if (th >  HPI)      th =  PI_F - th;
            else if (th < -HPI) th = -PI_F - th;
            out[row] = th;
        }
    }
}

// ---------------------------------------------------------------- launch
extern "C" void kernel_launch(void* const* d_in, const int* in_sizes, int n_in,
                              void* d_out, int out_size) {
    const float* x = (const float*)d_in[0];
    const float* w = (const float*)d_in[1];
    float* out = (float*)d_out;
    const int rows = in_sizes[0] / NFFT;
    if (rows <= 0) return;

    precompute_kernel<<<1, PRE_T>>>(w);

    int grid = (rows + 2 * WPB - 1) / (2 * WPB);   // ~2 rows per warp (R5 exact)
    if (grid < 1) grid = 1;
    dot_kernel<<<grid, TPB>>>(x, out, rows);
}

// round 13
// speedup vs baseline: 1.3951x; 1.0872x over previous
#include <cuda_runtime.h>
#include <math.h>

// ============================================================================
// PhasorTransformer, linear-algebra collapsed form.
//
// zf[0] = e^{i w31[0]} * sum_t e^{i w00[t]} * r[t] * e^{i x[t]},
//   r = F(m1 .* F(m2 .* F(m3)))  (F = unnormalized DFT, F^T = F; ortho
//   scalings drop out of angle; asin(sin(.)) = exact triangular wrap).
//
// Precompute = R6 float Stockham (best measured). Dot = R5 config (TPB 512,
// one row/warp, __ldg) + 2-deep rotating prefetch of the x loads only.
// ============================================================================

#define NFFT 2048

__device__ float g_rre[NFFT];
__device__ float g_rim[NFFT];

// ---------------------------------------------------------------- precompute
#define PRE_T 1024

__global__ void __launch_bounds__(PRE_T)
precompute_kernel(const float* __restrict__ w) {
    __shared__ float br[2][NFFT];
    __shared__ float bi[2][NFFT];
    __shared__ float twr[NFFT / 2];
    __shared__ float twi[NFFT / 2];
    const int tid = threadIdx.x;

    {   // twiddles exp(-2*pi*i*k/2048), k < 1024
        float a = -6.2831853071795864769f * (float)tid / (float)NFFT;
        float s, c;
        sincosf(a, &s, &c);
        twr[tid] = c;
        twi[tid] = s;
    }
    // buffer 0 = m3 = exp(i(w21 + w30))
#pragma unroll
    for (int k = 0; k < 2; k++) {
        int e = tid + PRE_T * k;
        float a = w[10240 + e] + w[12288 + e];
        float s, c;
        sincosf(a, &s, &c);
        br[0][e] = c;
        bi[0][e] = s;
    }
    __syncthreads();

    int cur = 0;
    for (int f = 0; f < 3; f++) {
        // 11 Stockham radix-2 stages, natural-order output, 1 butterfly/thread
        for (int t = 0; t < 11; t++) {
            const int s = 1 << t;
            const int nxt = cur ^ 1;
            const int n = tid;
            const int p = n >> t;
            const int q = n & (s - 1);
            const int j0 = q + (p << (t + 1));
            const int j1 = j0 + s;
            float ar = br[cur][n],             ai = bi[cur][n];
            float crr = br[cur][n + NFFT / 2], cii = bi[cur][n + NFFT / 2];
            float sr = ar + crr, si = ai + cii;
            float dr = ar - crr, di = ai - cii;
            float wr = twr[p << t], wi = twi[p << t];
            float er = fmaf(dr, wr, -di * wi);
            float ei = fmaf(dr, wi,  di * wr);
            br[nxt][j0] = sr; bi[nxt][j0] = si;
            br[nxt][j1] = er; bi[nxt][j1] = ei;
            cur = nxt;
            __syncthreads();
        }
        if (f < 2) {
            const int o1 = (f == 0) ? 6144 : 2048;
            const int o2 = (f == 0) ? 8192 : 4096;
#pragma unroll
            for (int k = 0; k < 2; k++) {
                int e = tid + PRE_T * k;
                float a = w[o1 + e] + w[o2 + e];
                float s, c;
                sincosf(a, &s, &c);
                float vr = br[cur][e], vi = bi[cur][e];
                br[cur][e] = fmaf(vr, c, -vi * s);
                bi[cur][e] = fmaf(vr, s,  vi * c);
            }
            __syncthreads();
        }
    }

    const float w310 = w[14336];
#pragma unroll
    for (int k = 0; k < 2; k++) {
        int e = tid + PRE_T * k;
        float a = w[e] + w310;
        float s, c;
        sincosf(a, &s, &c);
        float vr = br[cur][e], vi = bi[cur][e];
        g_rre[e] = fmaf(vr, c, -vi * s);
        g_rim[e] = fmaf(vr, s,  vi * c);
    }
}

// ---------------------------------------------------------------- main kernel
// warp-per-row complex dot product: S = sum_t r''[t] e^{i x[t]}
#define TPB 512
#define WPB (TPB / 32)

__device__ __forceinline__ void acc4(float4 xv, float4 rr, float4 ri,
                                     float& ax, float& ay) {
    float s, c;
    __sincosf(xv.x, &s, &c);
    ax = fmaf(rr.x, c, ax); ax = fmaf(-ri.x, s, ax);
    ay = fmaf(rr.x, s, ay); ay = fmaf( ri.x, c, ay);
    __sincosf(xv.y, &s, &c);
    ax = fmaf(rr.y, c, ax); ax = fmaf(-ri.y, s, ax);
    ay = fmaf(rr.y, s, ay); ay = fmaf( ri.y, c, ay);
    __sincosf(xv.z, &s, &c);
    ax = fmaf(rr.z, c, ax); ax = fmaf(-ri.z, s, ax);
    ay = fmaf(rr.z, s, ay); ay = fmaf( ri.z, c, ay);
    __sincosf(xv.w, &s, &c);
    ax = fmaf(rr.w, c, ax); ax = fmaf(-ri.w, s, ax);
    ay = fmaf(rr.w, s, ay); ay = fmaf( ri.w, c, ay);
}

__global__ void __launch_bounds__(TPB)
dot_kernel(const float* __restrict__ x, float* __restrict__ out, int rows) {
    __shared__ float sR[NFFT], sI[NFFT];
    const int tid = threadIdx.x;
    for (int i = tid; i < NFFT; i += TPB) {
        sR[i] = g_rre[i];
        sI[i] = g_rim[i];
    }
    __syncthreads();

    const int warp = tid >> 5;
    const int lane = tid & 31;
    const float4* sR4 = (const float4*)sR;
    const float4* sI4 = (const float4*)sI;

    for (int row = blockIdx.x * WPB + warp; row < rows; row += gridDim.x * WPB) {
        const float4* xr = (const float4*)(x + (size_t)row * NFFT);
        float ax = 0.f, ay = 0.f;

        // 2-deep rotating prefetch of x; table reads stay in the loop body.
        float4 x0 = __ldg(&xr[lane]);
        float4 x1 = __ldg(&xr[lane + 32]);
#pragma unroll
        for (int j = 0; j < 16; j++) {
            float4 xn = (j < 14) ? __ldg(&xr[lane + 32 * (j + 2)]) : x0;
            int e4 = lane + 32 * j;
            float4 rr = sR4[e4];
            float4 ri = sI4[e4];
            acc4(x0, rr, ri, ax, ay);
            x0 = x1;
            x1 = xn;
        }
#pragma unroll
        for (int off = 16; off > 0; off >>= 1) {
            ax += __shfl_xor_sync(0xffffffffu, ax, off);
            ay += __shfl_xor_sync(0xffffffffu, ay, off);
        }
        if (lane == 0) {
            float th = atan2f(ay, ax);
            const float PI_F = 3.14159265358979323846f;
            const float HPI  = 1.57079632679489661923f;
            if (th >  HPI)      th =  PI_F - th;
            else if (th < -HPI) th = -PI_F - th;
            out[row] = th;
        }
    }
}

// ---------------------------------------------------------------- launch
extern "C" void kernel_launch(void* const* d_in, const int* in_sizes, int n_in,
                              void* d_out, int out_size) {
    const float* x = (const float*)d_in[0];
    const float* w = (const float*)d_in[1];
    float* out = (float*)d_out;
    const int rows = in_sizes[0] / NFFT;
    if (rows <= 0) return;

    precompute_kernel<<<1, PRE_T>>>(w);

    int grid = (rows + WPB - 1) / WPB;     // one row per warp (R5-measured best)
    if (grid < 1) grid = 1;
    dot_kernel<<<grid, TPB>>>(x, out, rows);
}